// round 2
// baseline (speedup 1.0000x reference)
#include <cuda_runtime.h>
#include <cstdint>

#define D_MODEL 1024
#define NB 4
#define NCTA 128
#define ROWS_PER_CTA 8
#define NTHREADS 256
#define TP1_MAX 2049

// Persistent state: double-buffered hidden state + per-batch arrival counters.
__device__ float    g_hbuf[2][NB][D_MODEL];
__device__ unsigned g_ctr[NB * 32];   // 128B-padded counters

__global__ void rnn_init_kernel() {
    int i = blockIdx.x * blockDim.x + threadIdx.x;
    if (i < NB * 32) g_ctr[i] = 0u;
    if (i < 2 * NB * D_MODEL) reinterpret_cast<float*>(g_hbuf)[i] = 0.0f;
}

__device__ __forceinline__ unsigned ld_acquire_gpu(const unsigned* p) {
    unsigned v;
    asm volatile("ld.acquire.gpu.u32 %0, [%1];" : "=r"(v) : "l"(p) : "memory");
    return v;
}
__device__ __forceinline__ void red_release_add(unsigned* p, unsigned v) {
    asm volatile("red.release.gpu.global.add.u32 [%0], %1;" :: "l"(p), "r"(v) : "memory");
}

// One persistent CTA per 8 rows of W. W rows live in REGISTERS for the whole
// kernel. Units are (t, b): 4 independent batch recurrences are interleaved so
// the cross-CTA barrier for batch b step t is polled ~3 units after it was
// posted, hiding barrier + L2 latency.
__global__ void __launch_bounds__(NTHREADS, 1)
rnn_scan_kernel(const int*   __restrict__ ids,
                const float* __restrict__ emb,
                const float* __restrict__ W,
                float*       __restrict__ out,
                int Tp1)
{
    __shared__ int    ids_sm[NB * TP1_MAX];        // tokens incl. BOS
    __shared__ float4 hsm[2][D_MODEL / 4];         // staged h (one batch), dbl-buf
    __shared__ float  e_sm[NB * ROWS_PER_CTA];     // embedding slice for step t
    __shared__ float  psum[4][2];                  // cross-half partials

    const int tid  = threadIdx.x;
    const int w    = tid >> 5;
    const int lane = tid & 31;
    const int g    = w >> 1;      // row-pair group 0..3
    const int s    = w & 1;       // column half 0..1
    const int base = blockIdx.x * ROWS_PER_CTA;
    const int r0   = base + 2 * g;

    // ---- W tile -> registers (2 rows x 512 cols per warp; 32 floats/lane) ----
    const float4* __restrict__ Wv = reinterpret_cast<const float4*>(W);
    float4 wr0[4], wr1[4];
#pragma unroll
    for (int k = 0; k < 4; ++k) {
        int f4 = s * 128 + lane + 32 * k;
        wr0[k] = Wv[(size_t)r0 * 256 + f4];
        wr1[k] = Wv[(size_t)(r0 + 1) * 256 + f4];
    }

    // ---- stage token ids with BOS prepended ----
    const int T = Tp1 - 1;
    for (int i = tid; i < NB * Tp1; i += NTHREADS) {
        int b = i / Tp1;
        int t = i - b * Tp1;
        ids_sm[i] = (t == 0) ? 0 : ids[b * T + (t - 1)];
    }
    hsm[0][tid] = make_float4(0.f, 0.f, 0.f, 0.f);   // h_{-1} = 0 for unit 0
    __syncthreads();

    // ---- prefetch embedding slice for t = 0 (warp 0: lane -> (b, r)) ----
    float e_reg = 0.0f;
    if (w == 0) {
        int eb = lane >> 3, er = lane & 7;
        int tok = ids_sm[eb * Tp1];
        e_reg = emb[(size_t)tok * D_MODEL + base + er];
    }

    float4* hbufv = reinterpret_cast<float4*>(g_hbuf);   // [2][NB][256] float4
    const unsigned nunits = (unsigned)Tp1 * NB;

    for (unsigned u = 0; u < nunits; ++u) {
        const int t   = (int)(u >> 2);
        const int b   = (int)(u & 3);
        const int par = (int)(u & 1);
        const unsigned un = u + 1;
        const int tn = (int)(un >> 2), bn = (int)(un & 3);
        const bool have_next = (un < nunits);

        // Poll barrier for NEXT unit (its inputs were produced 4 units ago).
        if (tid == 0 && have_next && tn > 0) {
            const unsigned target = (unsigned)NCTA * (unsigned)tn;
            const unsigned* cp = &g_ctr[bn * 32];
            while (ld_acquire_gpu(cp) < target) { }
        }
        __syncthreads();   // (A) barrier confirmed; prev unit's writes ordered

        // Post arrival for the PREVIOUS unit (writes fenced before sync A).
        if (tid == 0 && u > 0) {
            red_release_add(&g_ctr[((u - 1) & 3) * 32], 1u);
        }

        // At b==0: publish e for this step, prefetch next step's e.
        if (b == 0 && w == 0) {
            e_sm[lane] = e_reg;
            if (t + 1 < Tp1) {
                int eb = lane >> 3, er = lane & 7;
                int tok = ids_sm[eb * Tp1 + t + 1];
                e_reg = emb[(size_t)tok * D_MODEL + base + er];
            }
        }

        // Prefetch h for next unit from global (latency hidden by FFMAs below).
        float4 hstage;
        if (have_next) {
            hstage = hbufv[((size_t)(tn & 1) * NB + bn) * 256 + tid];
        }

        // ---- matvec partials: 2 rows x 512 cols per warp ----
        const float4* __restrict__ h4 = hsm[par];
        float a0 = 0.f, a1 = 0.f;
#pragma unroll
        for (int k = 0; k < 4; ++k) {
            float4 hv = h4[s * 128 + lane + 32 * k];
            a0 += wr0[k].x * hv.x; a0 += wr0[k].y * hv.y;
            a0 += wr0[k].z * hv.z; a0 += wr0[k].w * hv.w;
            a1 += wr1[k].x * hv.x; a1 += wr1[k].y * hv.y;
            a1 += wr1[k].z * hv.z; a1 += wr1[k].w * hv.w;
        }
        if (have_next) hsm[par ^ 1][tid] = hstage;

        // warp-level reduce (all lanes end with full 512-col sums)
#pragma unroll
        for (int off = 16; off > 0; off >>= 1) {
            a0 += __shfl_xor_sync(0xffffffffu, a0, off);
            a1 += __shfl_xor_sync(0xffffffffu, a1, off);
        }
        if (s == 1 && lane == 0) { psum[g][0] = a0; psum[g][1] = a1; }
        __syncthreads();   // (B) partials + next-unit h stage visible

        // combine halves, add embedding, write new state + output
        if (s == 0 && lane < 2) {
            float v = (lane ? a1 : a0) + psum[g][lane] + e_sm[b * 8 + 2 * g + lane];
            int row = base + 2 * g + lane;
            g_hbuf[(t + 1) & 1][b][row] = v;
            out[((size_t)b * Tp1 + t) * D_MODEL + row] = v;
            __threadfence();
        }
        // arrival for this unit is posted after sync (A) of the next iteration
    }
}

extern "C" void kernel_launch(void* const* d_in, const int* in_sizes, int n_in,
                              void* d_out, int out_size) {
    const int*   ids = (const int*)d_in[0];
    const float* emb = (const float*)d_in[1];
    const float* W   = (const float*)d_in[2];
    float* out = (float*)d_out;

    int Tp1 = out_size / (NB * D_MODEL);   // 2049 for the reference shapes
    if (Tp1 > TP1_MAX) Tp1 = TP1_MAX;

    rnn_init_kernel<<<32, 256>>>();
    rnn_scan_kernel<<<NCTA, NTHREADS>>>(ids, emb, W, out, Tp1);
}

// round 3
// speedup vs baseline: 2.0912x; 2.0912x over previous
#include <cuda_runtime.h>
#include <cstdint>

#define D_MODEL 1024
#define NB 4
#define NCTA 128
#define NTHREADS 256          // 8 warps, one row per warp
#define TP1_MAX 2049

// Persistent cross-CTA state.
//  g_hbuf[slot][b][d] : hidden state, slot = t & 1 holds h_t.
//  g_tag[b][cta]      : tag = t+1 means "this CTA's rows of h_t are visible".
__device__ float                 g_hbuf[2][NB][D_MODEL];
__device__ __align__(16) unsigned g_tag[NB * NCTA];

__global__ void rnn_init_kernel() {
    int i = blockIdx.x * blockDim.x + threadIdx.x;
    if (i < NB * NCTA) g_tag[i] = 0u;
    if (i < 2 * NB * D_MODEL) reinterpret_cast<float*>(g_hbuf)[i] = 0.0f;
}

__device__ __forceinline__ uint4 ld_acquire_v4(const uint4* p) {
    uint4 v;
    asm volatile("ld.acquire.gpu.global.v4.u32 {%0,%1,%2,%3}, [%4];"
                 : "=r"(v.x), "=r"(v.y), "=r"(v.z), "=r"(v.w) : "l"(p) : "memory");
    return v;
}
__device__ __forceinline__ void st_release_u32(unsigned* p, unsigned v) {
    asm volatile("st.release.gpu.global.u32 [%0], %1;" :: "l"(p), "r"(v) : "memory");
}

// Persistent kernel. 128 CTAs x 8 rows. Units are (t, b): 4 independent batch
// recurrences interleaved so the cross-CTA dependency (distance 4 units) and
// the tag-publish -> tag-poll path (slack 2 units) stay off the critical path.
//
// Per-iteration schedule (ONE __syncthreads per unit):
//   entry: hsm[u&1] holds input of unit u; availability of unit u+1's input
//          in g_hbuf was confirmed by the poll in iteration u-1.
//   1. all warps: dot(W_row, hsm[u&1]) + shfl reduce
//   2. all threads: stage input of u+1 from g_hbuf (L1-bypassing)
//   3. warp 7: poll tags for unit u+2's input (published at u-2)
//   4. lane0/warp: v = dot + emb; write h to g_hbuf (+ out)
//   5. write stage into hsm[(u+1)&1]
//   6. __syncthreads
//   7. tid0: st.release tag = t+1   (barrier makes the release cumulative
//      over the other lanes' h stores -> no __threadfence needed)
__global__ void __launch_bounds__(NTHREADS, 1)
rnn_scan_kernel(const int*   __restrict__ ids,
                const float* __restrict__ emb,
                const float* __restrict__ W,
                float*       __restrict__ out,
                int Tp1)
{
    __shared__ int    ids_sm[NB * TP1_MAX];     // tokens incl. BOS
    __shared__ float4 hsm[2][D_MODEL / 4];      // staged h (one batch), dbl-buf

    const int tid  = threadIdx.x;
    const int w    = tid >> 5;
    const int lane = tid & 31;
    const int row  = blockIdx.x * 8 + w;        // this warp's W row

    // ---- W row -> registers: 32 floats/lane (cols 4*(lane + 32k)) ----
    const float4* __restrict__ Wv = reinterpret_cast<const float4*>(W);
    float4 wr[8];
#pragma unroll
    for (int k = 0; k < 8; ++k) wr[k] = Wv[(size_t)row * 256 + lane + 32 * k];

    // ---- stage token ids with BOS prepended ----
    const int T = Tp1 - 1;
    for (int i = tid; i < NB * Tp1; i += NTHREADS) {
        int b = i / Tp1;
        int t = i - b * Tp1;
        ids_sm[i] = (t == 0) ? 0 : ids[b * T + (t - 1)];
    }
    hsm[0][tid] = make_float4(0.f, 0.f, 0.f, 0.f);  // input of unit 0 (h_{-1}=0)
    __syncthreads();

    // ---- embedding prefetch: lane0 keeps e[b] for current + next step ----
    float e_cur[NB], e_next[NB];
    if (lane == 0) {
#pragma unroll
        for (int b = 0; b < NB; ++b)
            e_cur[b] = emb[(size_t)ids_sm[b * Tp1] * D_MODEL + row];
    }

    const float4* hbufv = reinterpret_cast<const float4*>(g_hbuf); // [2][NB][256]
    const unsigned nunits = (unsigned)Tp1 * NB;

    for (unsigned u = 0; u < nunits; ++u) {
        const int t = (int)(u >> 2);
        const int b = (int)(u & 3);
        const int q = (int)(u & 1);

        // ---- 1. matvec: full row per warp, 4 accumulators ----
        const float4* __restrict__ h4 = hsm[q];
        float a0 = 0.f, a1 = 0.f, a2 = 0.f, a3 = 0.f;
#pragma unroll
        for (int k = 0; k < 8; k += 4) {
            float4 h0 = h4[lane + 32 * (k + 0)];
            float4 h1 = h4[lane + 32 * (k + 1)];
            float4 h2 = h4[lane + 32 * (k + 2)];
            float4 h3 = h4[lane + 32 * (k + 3)];
            a0 += wr[k + 0].x * h0.x; a0 += wr[k + 0].y * h0.y;
            a0 += wr[k + 0].z * h0.z; a0 += wr[k + 0].w * h0.w;
            a1 += wr[k + 1].x * h1.x; a1 += wr[k + 1].y * h1.y;
            a1 += wr[k + 1].z * h1.z; a1 += wr[k + 1].w * h1.w;
            a2 += wr[k + 2].x * h2.x; a2 += wr[k + 2].y * h2.y;
            a2 += wr[k + 2].z * h2.z; a2 += wr[k + 2].w * h2.w;
            a3 += wr[k + 3].x * h3.x; a3 += wr[k + 3].y * h3.y;
            a3 += wr[k + 3].z * h3.z; a3 += wr[k + 3].w * h3.w;
        }
        float a = (a0 + a1) + (a2 + a3);

        // ---- 2. stage input of unit u+1 (poll for it succeeded in iter u-1) ----
        const unsigned un = u + 1;
        const bool have_next = (un < nunits);
        float4 hstage;
        if (have_next) {
            const int tn = (int)(un >> 2), bn = (int)(un & 3);
            const int slot = (tn + 1) & 1;               // h_{tn-1} lives here
            hstage = __ldcg(&hbufv[((size_t)slot * NB + bn) * 256 + tid]);
        }

        // ---- warp reduce (5 shfls) ----
#pragma unroll
        for (int off = 16; off > 0; off >>= 1)
            a += __shfl_xor_sync(0xffffffffu, a, off);

        // ---- 3. warp 7: poll tags for unit u+2's input ----
        if (w == 7) {
            const unsigned u2 = u + 2;
            if (u2 < nunits) {
                const int t2 = (int)(u2 >> 2), b2 = (int)(u2 & 3);
                if (t2 > 0) {
                    const uint4* tp =
                        reinterpret_cast<const uint4*>(g_tag + b2 * NCTA) + lane;
                    const unsigned need = (unsigned)t2;
                    for (;;) {
                        uint4 v = ld_acquire_v4(tp);
                        unsigned m = min(min(v.x, v.y), min(v.z, v.w));
                        if (__all_sync(0xffffffffu, m >= need)) break;
                    }
                }
            }
        }

        // ---- 4. epilogue: h_t = dot + emb ----
        if (lane == 0) {
            float v = a + e_cur[b];
            __stcg(&g_hbuf[t & 1][b][row], v);
            out[((size_t)b * Tp1 + t) * D_MODEL + row] = v;
            // embedding prefetch for step t+1 (3 units of slack)
            if (b == 0 && t + 1 < Tp1) {
#pragma unroll
                for (int bb = 0; bb < NB; ++bb)
                    e_next[bb] = emb[(size_t)ids_sm[bb * Tp1 + t + 1] * D_MODEL + row];
            }
            if (b == 3) {
#pragma unroll
                for (int bb = 0; bb < NB; ++bb) e_cur[bb] = e_next[bb];
            }
        }

        // ---- 5. publish stage into the other smem buffer ----
        if (have_next) hsm[q ^ 1][tid] = hstage;

        // ---- 6. single barrier ----
        __syncthreads();

        // ---- 7. release tag: h_t (this CTA's rows) is now globally visible ----
        if (tid == 0) st_release_u32(&g_tag[b * NCTA + blockIdx.x], (unsigned)(t + 1));
    }
}

extern "C" void kernel_launch(void* const* d_in, const int* in_sizes, int n_in,
                              void* d_out, int out_size) {
    const int*   ids = (const int*)d_in[0];
    const float* emb = (const float*)d_in[1];
    const float* W   = (const float*)d_in[2];
    float* out = (float*)d_out;

    int Tp1 = out_size / (NB * D_MODEL);   // 2049 for the reference shapes
    if (Tp1 > TP1_MAX) Tp1 = TP1_MAX;

    rnn_init_kernel<<<32, 256>>>();
    rnn_scan_kernel<<<NCTA, NTHREADS>>>(ids, emb, W, out, Tp1);
}

// round 4
// speedup vs baseline: 2.1915x; 1.0479x over previous
#include <cuda_runtime.h>
#include <cstdint>

#define D_MODEL 1024
#define NB 4
#define NCTA 128
#define NTHREADS 256          // 8 warps, one row per warp
#define TP1_MAX 2049

// Persistent cross-CTA state.
//  g_hbuf[slot][b][d] : hidden state, slot = t & 1 holds h_t.
//  g_tag[b][cta]      : tag = t+1 means "this CTA's rows of h_t are visible".
__device__ float                  g_hbuf[2][NB][D_MODEL];
__device__ __align__(16) unsigned g_tag[NB * NCTA];

__global__ void rnn_init_kernel() {
    int i = blockIdx.x * blockDim.x + threadIdx.x;
    if (i < NB * NCTA) g_tag[i] = 0u;
    if (i < 2 * NB * D_MODEL) reinterpret_cast<float*>(g_hbuf)[i] = 0.0f;
}

__device__ __forceinline__ uint4 ld_acquire_v4(const uint4* p) {
    uint4 v;
    asm volatile("ld.acquire.gpu.global.v4.u32 {%0,%1,%2,%3}, [%4];"
                 : "=r"(v.x), "=r"(v.y), "=r"(v.z), "=r"(v.w) : "l"(p) : "memory");
    return v;
}
__device__ __forceinline__ void st_release_u32(unsigned* p, unsigned v) {
    asm volatile("st.release.gpu.global.u32 [%0], %1;" :: "l"(p), "r"(v) : "memory");
}

// Persistent kernel. 128 CTAs x 8 rows, units (t, b) over 4 interleaved batch
// chains (dependency distance = 4 units).
//
// KEY CHANGE vs R3: both L2 round trips are split transactions. The tag probe
// (for unit u+2's input) and the h-stage load (unit u+1's input) are ISSUED at
// the top of the iteration and CONSUMED at the bottom, so their ~260-cycle L2
// latency is hidden under the matvec + reduce instead of sitting on the
// __syncthreads critical path.
__global__ void __launch_bounds__(NTHREADS, 1)
rnn_scan_kernel(const int*   __restrict__ ids,
                const float* __restrict__ emb,
                const float* __restrict__ W,
                float*       __restrict__ out,
                int Tp1)
{
    __shared__ int    ids_sm[NB * TP1_MAX];     // tokens incl. BOS
    __shared__ float4 hsm[2][D_MODEL / 4];      // staged h (one batch), dbl-buf

    const int tid  = threadIdx.x;
    const int w    = tid >> 5;
    const int lane = tid & 31;
    const int row  = blockIdx.x * 8 + w;        // this warp's W row

    // ---- W row -> registers: 32 floats/lane (cols 4*(lane + 32k)) ----
    const float4* __restrict__ Wv = reinterpret_cast<const float4*>(W);
    float4 wr[8];
#pragma unroll
    for (int k = 0; k < 8; ++k) wr[k] = Wv[(size_t)row * 256 + lane + 32 * k];

    // ---- stage token ids with BOS prepended ----
    const int T = Tp1 - 1;
    for (int i = tid; i < NB * Tp1; i += NTHREADS) {
        int b = i / Tp1;
        int t = i - b * Tp1;
        ids_sm[i] = (t == 0) ? 0 : ids[b * T + (t - 1)];
    }
    hsm[0][tid] = make_float4(0.f, 0.f, 0.f, 0.f);  // input of unit 0 (h_{-1}=0)
    __syncthreads();

    // ---- embedding prefetch: lane0 keeps e[b] for current + next step ----
    float e_cur[NB], e_next[NB];
    if (lane == 0) {
#pragma unroll
        for (int b = 0; b < NB; ++b)
            e_cur[b] = emb[(size_t)ids_sm[b * Tp1] * D_MODEL + row];
    }

    const float4* hbufv = reinterpret_cast<const float4*>(g_hbuf); // [2][NB][256]
    const unsigned nunits = (unsigned)Tp1 * NB;

    for (unsigned u = 0; u < nunits; ++u) {
        const int t = (int)(u >> 2);
        const int b = (int)(u & 3);
        const int q = (int)(u & 1);

        // ---- A. issue tag probe for unit u+2's input (warp 7, split txn) ----
        const unsigned u2 = u + 2;
        const bool do_poll = (w == 7) && (u2 < nunits) && (u2 >= 4 * 1);
        uint4 probe = make_uint4(0xffffffffu, 0xffffffffu, 0xffffffffu, 0xffffffffu);
        const uint4* tagp = nullptr;
        unsigned need = 0;
        if (do_poll) {
            const int t2 = (int)(u2 >> 2), b2 = (int)(u2 & 3);
            if (t2 > 0) {
                tagp = reinterpret_cast<const uint4*>(g_tag + b2 * NCTA) + lane;
                need = (unsigned)t2;
                probe = ld_acquire_v4(tagp);      // issued now, checked at F
            }
        }

        // ---- B. issue h-stage load for unit u+1's input (split txn) ----
        const unsigned un = u + 1;
        const bool have_next = (un < nunits);
        float4 hstage;
        if (have_next) {
            const int tn = (int)(un >> 2), bn = (int)(un & 3);
            const int slot = (tn + 1) & 1;               // h_{tn-1} lives here
            hstage = __ldcg(&hbufv[((size_t)slot * NB + bn) * 256 + tid]);
        }

        // ---- C. matvec: full row per warp, 4 accumulators ----
        const float4* __restrict__ h4 = hsm[q];
        float a0 = 0.f, a1 = 0.f, a2 = 0.f, a3 = 0.f;
#pragma unroll
        for (int k = 0; k < 8; k += 4) {
            float4 h0 = h4[lane + 32 * (k + 0)];
            float4 h1 = h4[lane + 32 * (k + 1)];
            float4 h2 = h4[lane + 32 * (k + 2)];
            float4 h3 = h4[lane + 32 * (k + 3)];
            a0 += wr[k + 0].x * h0.x; a0 += wr[k + 0].y * h0.y;
            a0 += wr[k + 0].z * h0.z; a0 += wr[k + 0].w * h0.w;
            a1 += wr[k + 1].x * h1.x; a1 += wr[k + 1].y * h1.y;
            a1 += wr[k + 1].z * h1.z; a1 += wr[k + 1].w * h1.w;
            a2 += wr[k + 2].x * h2.x; a2 += wr[k + 2].y * h2.y;
            a2 += wr[k + 2].z * h2.z; a2 += wr[k + 2].w * h2.w;
            a3 += wr[k + 3].x * h3.x; a3 += wr[k + 3].y * h3.y;
            a3 += wr[k + 3].z * h3.z; a3 += wr[k + 3].w * h3.w;
        }
        float a = (a0 + a1) + (a2 + a3);

        // ---- warp reduce (5 shfls) ----
#pragma unroll
        for (int off = 16; off > 0; off >>= 1)
            a += __shfl_xor_sync(0xffffffffu, a, off);

        // ---- D. epilogue: h_t = dot + emb ----
        if (lane == 0) {
            float v = a + e_cur[b];
            __stcg(&g_hbuf[t & 1][b][row], v);
            out[((size_t)b * Tp1 + t) * D_MODEL + row] = v;
            // embedding prefetch for step t+1 (3 units of slack)
            if (b == 0 && t + 1 < Tp1) {
#pragma unroll
                for (int bb = 0; bb < NB; ++bb)
                    e_next[bb] = emb[(size_t)ids_sm[bb * Tp1 + t + 1] * D_MODEL + row];
            }
            if (b == 3) {
#pragma unroll
                for (int bb = 0; bb < NB; ++bb) e_cur[bb] = e_next[bb];
            }
        }

        // ---- E. consume stage: publish into the other smem buffer ----
        if (have_next) hsm[q ^ 1][tid] = hstage;

        // ---- F. check probe; retry only on a genuine miss ----
        if (tagp) {
            unsigned m = min(min(probe.x, probe.y), min(probe.z, probe.w));
            while (!__all_sync(0xffffffffu, m >= need)) {
                uint4 v = ld_acquire_v4(tagp);
                m = min(min(v.x, v.y), min(v.z, v.w));
            }
        }

        // ---- G. single barrier ----
        __syncthreads();

        // ---- H. release tag: h_t (this CTA's rows) now globally visible ----
        if (tid == 0) st_release_u32(&g_tag[b * NCTA + blockIdx.x], (unsigned)(t + 1));
    }
}

extern "C" void kernel_launch(void* const* d_in, const int* in_sizes, int n_in,
                              void* d_out, int out_size) {
    const int*   ids = (const int*)d_in[0];
    const float* emb = (const float*)d_in[1];
    const float* W   = (const float*)d_in[2];
    float* out = (float*)d_out;

    int Tp1 = out_size / (NB * D_MODEL);   // 2049 for the reference shapes
    if (Tp1 > TP1_MAX) Tp1 = TP1_MAX;

    rnn_init_kernel<<<32, 256>>>();
    rnn_scan_kernel<<<NCTA, NTHREADS>>>(ids, emb, W, out, Tp1);
}